// round 6
// baseline (speedup 1.0000x reference)
#include <cuda_runtime.h>
#include <cuda_bf16.h>
#include <math.h>
#include <stdint.h>

#define Bsz 8192
#define Gd  1024
#define Ed  256
#define Kd  2048
#define PNULL 0.1f

// ---------------- scratch (device globals; no allocs allowed) ----------------
__device__ __nv_bfloat16  g_pik  [(size_t)Bsz * Kd];    // 32 MB (unnormalized exp)
__device__ __nv_bfloat16  g_w    [(size_t)Bsz * Kd];    // 32 MB: w / u scratch
__device__ __nv_bfloat16  g_z    [(size_t)Bsz * Ed];    // 4 MB
__device__ __nv_bfloat16  g_imgs [(size_t)Bsz * Gd];    // 16 MB
__device__ __nv_bfloat16  g_xa   [(size_t)Gd * Kd];     // (G,K)
__device__ __nv_bfloat16  g_xaT  [(size_t)Kd * Gd];     // (K,G)
__device__ __nv_bfloat16  g_xb   [(size_t)Ed * Kd];     // (E,K)
__device__ __nv_bfloat16  g_xbT  [(size_t)Kd * Ed];     // (K,E)
__device__ float g_c2a[Kd], g_c2b[Kd], g_sums[Bsz], g_z2[Bsz];

// ---------------- helpers ----------------
__device__ __forceinline__ uint32_t s2u(const void* p) {
    uint32_t a;
    asm("{ .reg .u64 t; cvta.to.shared.u64 t, %1; cvt.u32.u64 %0, t; }" : "=r"(a) : "l"(p));
    return a;
}
#define SWZ(o) ((o) ^ (((o) >> 3) & 0x70))

__device__ __forceinline__ void cp16(uint32_t dst, const void* src) {
    asm volatile("cp.async.cg.shared.global [%0], [%1], 16;" :: "r"(dst), "l"(src));
}
#define CP_COMMIT()   asm volatile("cp.async.commit_group;" ::: "memory")
#define CP_WAIT(n)    asm volatile("cp.async.wait_group %0;" :: "n"(n) : "memory")

#define LDSM4(r, addr)                                                              \
    asm volatile("ldmatrix.sync.aligned.m8n8.x4.shared.b16 {%0,%1,%2,%3}, [%4];"    \
        : "=r"((r)[0]), "=r"((r)[1]), "=r"((r)[2]), "=r"((r)[3]) : "r"(addr))

#define MMA(d, a, b0, b1)                                                           \
    asm volatile("mma.sync.aligned.m16n8k16.row.col.f32.bf16.bf16.f32 "             \
        "{%0,%1,%2,%3}, {%4,%5,%6,%7}, {%8,%9}, {%0,%1,%2,%3};"                     \
        : "+f"((d)[0]), "+f"((d)[1]), "+f"((d)[2]), "+f"((d)[3])                    \
        : "r"((a)[0]), "r"((a)[1]), "r"((a)[2]), "r"((a)[3]), "r"(b0), "r"(b1))

// ---------------- mma.sync GEMM: D[(MI*64) x 128] tile = A(MxK,K-major) . B(NxK,K-major)^T
// MI=2: 128x128 tile, warp 32x64, 2 CTA/SM.  MI=4: 256x128 tile, warp 64x64, 1 CTA/SM.
// EPI 0: e = exp(acc*alpha - c2[n]); out=e (bf16); redout[m] += sum_n e   (pik gen)
//     1: out = acc / rowvec[m]                                            (z)
//     2: w = pik[m,n]*exp(acc*alpha - c2[n]); out=w; redout[m] += sum w   (w)
//     3: u = exp(acc*alpha - c2[n] - rowvec[m]); out=u; redout[m] += sum  (u, rowvec=z2)
//     4: d = acc/(PNULL+rowvec[m]) - images[m,n]; redout[m] += d^2/G      (loss)
//     5: t = acc / rowvec[m]; out=t; redout[m] += t^2/E                   (z + z2)
template <int MI, int EPI>
__global__ void __launch_bounds__(256, (MI == 2) ? 2 : 1)
mma_gemm(const __nv_bfloat16* __restrict__ A, const __nv_bfloat16* __restrict__ Bm,
         int Kin, int lda, int ldb, int ldc, float alpha,
         __nv_bfloat16* __restrict__ out_bf16,
         const __nv_bfloat16* __restrict__ pik,
         const float* __restrict__ c2vec, const float* __restrict__ rowvec,
         const float* __restrict__ images, float* __restrict__ redout)
{
    extern __shared__ char smem[];
    constexpr int MTILE = MI * 64;
    constexpr uint32_t A_ST = MTILE * 128;          // bytes per A stage
    constexpr uint32_t B_OFF = 3 * A_ST;            // B stages base
    const uint32_t sb = s2u(smem);
    const int tid = threadIdx.x, wid = tid >> 5, lane = tid & 31;
    const int m0 = blockIdx.y * MTILE, n0 = blockIdx.x * 128;
    const int wm = (wid & 3) * (MI * 16), wn = (wid >> 2) * 64;

    float acc[MI][8][4];
#pragma unroll
    for (int i = 0; i < MI; i++)
#pragma unroll
        for (int j = 0; j < 8; j++)
#pragma unroll
            for (int q = 0; q < 4; q++) acc[i][j][q] = 0.f;

    auto loadA = [&](int c, int st) {
        // one stage = MTILE rows x 128 B = MTILE*8 16B-units; 256 threads -> MI*2 per thread
#pragma unroll
        for (int u = 0; u < MI * 2; u++) {
            int unit = tid + u * 256;                      // 0..MTILE*8-1
            int row = unit >> 3, seg = unit & 7;
            cp16(sb + st * A_ST + SWZ((uint32_t)(row * 128 + seg * 16)),
                 (const char*)(A + (size_t)(m0 + row) * lda + c * 64) + seg * 16);
        }
    };
    auto loadB = [&](int c, int st) {
#pragma unroll
        for (int u = 0; u < 4; u++) {
            int unit = tid + u * 256;                      // 0..1023 (128 rows x 8 segs)
            int row = unit >> 3, seg = unit & 7;
            cp16(sb + B_OFF + st * 16384 + SWZ((uint32_t)(row * 128 + seg * 16)),
                 (const char*)(Bm + (size_t)(n0 + row) * ldb + c * 64) + seg * 16);
        }
    };

    const int nch = Kin >> 6;
    loadA(0, 0); loadB(0, 0); CP_COMMIT();
    if (nch > 1) { loadA(1, 1); loadB(1, 1); CP_COMMIT(); }

    const int lr = lane & 15, lc = (lane >> 4) * 16;

    for (int c = 0; c < nch; c++) {
        if (c == nch - 1) { CP_WAIT(0); } else { CP_WAIT(1); }
        __syncthreads();                       // stage c visible; stage (c+2)%3 compute done
        if (c + 2 < nch) {
            loadA(c + 2, (c + 2) % 3); loadB(c + 2, (c + 2) % 3); CP_COMMIT();
        }
        const int st = c % 3;
        const uint32_t sA = sb + st * A_ST;
        const uint32_t sB = sb + B_OFF + st * 16384;
#pragma unroll
        for (int kk = 0; kk < 4; kk++) {
            const int kb = kk * 32 + lc;
            uint32_t a[MI][4], b[4][4];
#pragma unroll
            for (int mi = 0; mi < MI; mi++)
                LDSM4(a[mi], sA + SWZ((uint32_t)((wm + mi * 16 + lr) * 128 + kb)));
#pragma unroll
            for (int pi = 0; pi < 4; pi++)
                LDSM4(b[pi], sB + SWZ((uint32_t)((wn + pi * 16 + lr) * 128 + kb)));
#pragma unroll
            for (int mi = 0; mi < MI; mi++)
#pragma unroll
                for (int ni = 0; ni < 8; ni++) {
                    const int pi = ni >> 1, sel = ni & 1;
                    MMA(acc[mi][ni], a[mi], b[pi][sel], b[pi][sel + 2]);
                }
        }
    }

    // ---- epilogue ----
    const int g = lane >> 2, cq = lane & 3;
    constexpr float rscale = (EPI == 4) ? 1.0f / Gd : (EPI == 5) ? 1.0f / Ed : 1.0f;
#pragma unroll
    for (int mi = 0; mi < MI; mi++) {
        const int r0 = m0 + wm + mi * 16 + g;
        const int r1 = r0 + 8;
        float rv0 = 1.f, rv1 = 1.f;
        if (EPI == 1 || EPI == 5) { rv0 = 1.0f / rowvec[r0]; rv1 = 1.0f / rowvec[r1]; }
        if (EPI == 3) { rv0 = rowvec[r0]; rv1 = rowvec[r1]; }
        if (EPI == 4) { rv0 = 1.0f / (PNULL + rowvec[r0]); rv1 = 1.0f / (PNULL + rowvec[r1]); }
        float ls0 = 0.f, ls1 = 0.f;
#pragma unroll
        for (int ni = 0; ni < 8; ni++) {
            const int col = n0 + wn + ni * 8 + cq * 2;
            float v00 = acc[mi][ni][0], v01 = acc[mi][ni][1];
            float v10 = acc[mi][ni][2], v11 = acc[mi][ni][3];
            size_t i0 = (size_t)r0 * ldc + col, i1 = (size_t)r1 * ldc + col;
            if (EPI == 0) {
                float c0 = c2vec[col], c1 = c2vec[col + 1];
                float e00 = expf(v00 * alpha - c0), e01 = expf(v01 * alpha - c1);
                float e10 = expf(v10 * alpha - c0), e11 = expf(v11 * alpha - c1);
                *(__nv_bfloat162*)(out_bf16 + i0) = __floats2bfloat162_rn(e00, e01);
                *(__nv_bfloat162*)(out_bf16 + i1) = __floats2bfloat162_rn(e10, e11);
                ls0 += e00 + e01; ls1 += e10 + e11;
            } else if (EPI == 1) {
                *(__nv_bfloat162*)(out_bf16 + i0) = __floats2bfloat162_rn(v00 * rv0, v01 * rv0);
                *(__nv_bfloat162*)(out_bf16 + i1) = __floats2bfloat162_rn(v10 * rv1, v11 * rv1);
            } else if (EPI == 5) {
                float t00 = v00 * rv0, t01 = v01 * rv0;
                float t10 = v10 * rv1, t11 = v11 * rv1;
                *(__nv_bfloat162*)(out_bf16 + i0) = __floats2bfloat162_rn(t00, t01);
                *(__nv_bfloat162*)(out_bf16 + i1) = __floats2bfloat162_rn(t10, t11);
                ls0 += t00 * t00 + t01 * t01; ls1 += t10 * t10 + t11 * t11;
            } else if (EPI == 2) {
                float c0 = c2vec[col], c1 = c2vec[col + 1];
                __nv_bfloat162 p0 = *(const __nv_bfloat162*)(pik + i0);
                __nv_bfloat162 p1 = *(const __nv_bfloat162*)(pik + i1);
                float w00 = __bfloat162float(p0.x) * expf(v00 * alpha - c0);
                float w01 = __bfloat162float(p0.y) * expf(v01 * alpha - c1);
                float w10 = __bfloat162float(p1.x) * expf(v10 * alpha - c0);
                float w11 = __bfloat162float(p1.y) * expf(v11 * alpha - c1);
                *(__nv_bfloat162*)(out_bf16 + i0) = __floats2bfloat162_rn(w00, w01);
                *(__nv_bfloat162*)(out_bf16 + i1) = __floats2bfloat162_rn(w10, w11);
                ls0 += w00 + w01; ls1 += w10 + w11;
            } else if (EPI == 3) {
                float c0 = c2vec[col], c1 = c2vec[col + 1];
                float u00 = expf(v00 * alpha - c0 - rv0), u01 = expf(v01 * alpha - c1 - rv0);
                float u10 = expf(v10 * alpha - c0 - rv1), u11 = expf(v11 * alpha - c1 - rv1);
                *(__nv_bfloat162*)(out_bf16 + i0) = __floats2bfloat162_rn(u00, u01);
                *(__nv_bfloat162*)(out_bf16 + i1) = __floats2bfloat162_rn(u10, u11);
                ls0 += u00 + u01; ls1 += u10 + u11;
            } else {  // EPI 4
                float d;
                d = v00 * rv0 - images[i0];     ls0 += d * d;
                d = v01 * rv0 - images[i0 + 1]; ls0 += d * d;
                d = v10 * rv1 - images[i1];     ls1 += d * d;
                d = v11 * rv1 - images[i1 + 1]; ls1 += d * d;
            }
        }
        if (EPI != 1) {
            ls0 += __shfl_xor_sync(0xffffffffu, ls0, 1);
            ls0 += __shfl_xor_sync(0xffffffffu, ls0, 2);
            ls1 += __shfl_xor_sync(0xffffffffu, ls1, 1);
            ls1 += __shfl_xor_sync(0xffffffffu, ls1, 2);
            if (cq == 0) {
                atomicAdd(&redout[r0], ls0 * rscale);
                atomicAdd(&redout[r1], ls1 * rscale);
            }
        }
    }
}

// ---------------- small kernels ----------------
__global__ void k_cvt4(const float4* __restrict__ s, __nv_bfloat162* __restrict__ d, int n4) {
    int i = blockIdx.x * blockDim.x + threadIdx.x;
    if (i < n4) {
        float4 v = s[i];
        d[2 * i]     = __floats2bfloat162_rn(v.x, v.y);
        d[2 * i + 1] = __floats2bfloat162_rn(v.z, v.w);
    }
}
// tiled transpose+convert: dst (C,R) bf16 = src (R,C)^T fp32
__global__ void k_tcvtT(const float* __restrict__ s, __nv_bfloat16* __restrict__ d, int R, int C) {
    __shared__ float t[32][33];
    int c0 = blockIdx.x * 32, r0 = blockIdx.y * 32;
    int tx = threadIdx.x, ty = threadIdx.y;       // block (32,8)
#pragma unroll
    for (int j = 0; j < 32; j += 8) t[ty + j][tx] = s[(size_t)(r0 + ty + j) * C + c0 + tx];
    __syncthreads();
#pragma unroll
    for (int j = 0; j < 32; j += 8)
        d[(size_t)(c0 + ty + j) * R + r0 + tx] = __float2bfloat16(t[tx][ty + j]);
}
__global__ void k_c2(const float* __restrict__ xa, const float* __restrict__ xb) {
    int k = blockIdx.x * blockDim.x + threadIdx.x;
    if (k >= Kd) return;
    float s = 0.f;
    for (int g = 0; g < Gd; g++) { float v = xa[(size_t)g * Kd + k]; s += v * v; }
    g_c2a[k] = s / Gd;
    float t = 0.f;
    for (int e = 0; e < Ed; e++) { float v = xb[(size_t)e * Kd + k]; t += v * v; }
    g_c2b[k] = t / Ed;
}

// ---------------- host ----------------
extern "C" void kernel_launch(void* const* d_in, const int* in_sizes, int n_in,
                              void* d_out, int out_size) {
    (void)in_sizes; (void)n_in; (void)out_size;
    const float* images = (const float*)d_in[0];
    const float* xa     = (const float*)d_in[1];
    const float* xb     = (const float*)d_in[2];
    float* loss = (float*)d_out;

    float *c2a, *c2b, *sums, *z2;
    __nv_bfloat16 *pik, *wb, *zb, *imgs, *xab, *xaT, *xbb, *xbT;
    cudaGetSymbolAddress((void**)&pik,  g_pik);
    cudaGetSymbolAddress((void**)&wb,   g_w);
    cudaGetSymbolAddress((void**)&zb,   g_z);
    cudaGetSymbolAddress((void**)&imgs, g_imgs);
    cudaGetSymbolAddress((void**)&xab,  g_xa);
    cudaGetSymbolAddress((void**)&xaT,  g_xaT);
    cudaGetSymbolAddress((void**)&xbb,  g_xb);
    cudaGetSymbolAddress((void**)&xbT,  g_xbT);
    cudaGetSymbolAddress((void**)&c2a,  g_c2a);
    cudaGetSymbolAddress((void**)&c2b,  g_c2b);
    cudaGetSymbolAddress((void**)&sums, g_sums);
    cudaGetSymbolAddress((void**)&z2,   g_z2);

    const int SMEM2 = 3 * (128 * 128) + 3 * 16384;   // 96 KB (MI=2)
    const int SMEM4 = 3 * (256 * 128) + 3 * 16384;   // 144 KB (MI=4)
    cudaFuncSetAttribute(mma_gemm<4, 0>, cudaFuncAttributeMaxDynamicSharedMemorySize, SMEM4);
    cudaFuncSetAttribute(mma_gemm<2, 1>, cudaFuncAttributeMaxDynamicSharedMemorySize, SMEM2);
    cudaFuncSetAttribute(mma_gemm<4, 2>, cudaFuncAttributeMaxDynamicSharedMemorySize, SMEM4);
    cudaFuncSetAttribute(mma_gemm<4, 3>, cudaFuncAttributeMaxDynamicSharedMemorySize, SMEM4);
    cudaFuncSetAttribute(mma_gemm<4, 4>, cudaFuncAttributeMaxDynamicSharedMemorySize, SMEM4);
    cudaFuncSetAttribute(mma_gemm<2, 5>, cudaFuncAttributeMaxDynamicSharedMemorySize, SMEM2);

    // one-time conversions
    k_cvt4<<<(Bsz * Gd / 4 + 255) / 256, 256>>>((const float4*)images, (__nv_bfloat162*)imgs, Bsz * Gd / 4);
    k_cvt4<<<(Gd * Kd / 4 + 255) / 256, 256>>>((const float4*)xa, (__nv_bfloat162*)xab, Gd * Kd / 4);
    k_cvt4<<<(Ed * Kd / 4 + 255) / 256, 256>>>((const float4*)xb, (__nv_bfloat162*)xbb, Ed * Kd / 4);
    k_tcvtT<<<dim3(Kd / 32, Gd / 32), dim3(32, 8)>>>(xa, xaT, Gd, Kd);  // (K,G)
    k_tcvtT<<<dim3(Kd / 32, Ed / 32), dim3(32, 8)>>>(xb, xbT, Ed, Kd);  // (K,E)
    k_c2<<<Kd / 256, 256>>>(xa, xb);

    dim3 gK(Kd / 128, Bsz / 256);   // (16,32) MI=4
    dim3 gE(Ed / 128, Bsz / 128);   // (2,64)  MI=2
    dim3 gG(Gd / 128, Bsz / 256);   // (8,32)  MI=4

    // pik_unnorm = exp(images@xa*2/G - c2a), sums = row sums (softmax denominator)
    cudaMemsetAsync(sums, 0, Bsz * sizeof(float));
    mma_gemm<4, 0><<<gK, 256, SMEM4>>>(imgs, xaT, Gd, Gd, Gd, Kd, 2.0f / Gd,
                                       pik, nullptr, c2a, nullptr, nullptr, sums);
    // z = (pik_unnorm @ xb^T) / sums   (== softmax(pik) @ xb^T)
    mma_gemm<2, 1><<<gE, 256, SMEM2>>>(pik, xbb, Kd, Kd, Kd, Ed, 1.0f,
                                       zb, nullptr, nullptr, sums, nullptr, nullptr);
    // 4 EM steps; P_NULL and exp(-z2) row constants cancel in xp = w/sum(w)
    for (int s = 0; s < 4; s++) {
        cudaMemsetAsync(sums, 0, Bsz * sizeof(float));
        // w = pik * exp((z@xb)*2/E - c2b); sums = row sums(w)
        mma_gemm<4, 2><<<gK, 256, SMEM4>>>(zb, xbT, Ed, Ed, Ed, Kd, 2.0f / Ed,
                                           wb, pik, c2b, nullptr, nullptr, sums);
        if (s < 3) {
            mma_gemm<2, 1><<<gE, 256, SMEM2>>>(wb, xbb, Kd, Kd, Kd, Ed, 1.0f,
                                               zb, nullptr, nullptr, sums, nullptr, nullptr);
        } else {
            // last step also accumulates z2 = mean_e z^2 for decode
            cudaMemsetAsync(z2, 0, Bsz * sizeof(float));
            mma_gemm<2, 5><<<gE, 256, SMEM2>>>(wb, xbb, Kd, Kd, Kd, Ed, 1.0f,
                                               zb, nullptr, nullptr, sums, nullptr, z2);
        }
    }
    // decode: u = exp((z@xb)*2/E - c2b - z2); sums = row sums(u)
    cudaMemsetAsync(sums, 0, Bsz * sizeof(float));
    mma_gemm<4, 3><<<gK, 256, SMEM4>>>(zb, xbT, Ed, Ed, Ed, Kd, 2.0f / Ed,
                                       wb, nullptr, c2b, z2, nullptr, sums);
    // loss[b] = mean_g ((u/(0.1+sums)) @ xa^T - images)^2
    cudaMemsetAsync(loss, 0, Bsz * sizeof(float));
    mma_gemm<4, 4><<<gG, 256, SMEM4>>>(wb, xab, Kd, Kd, Kd, Gd, 1.0f,
                                       nullptr, nullptr, nullptr, sums, images, loss);
}

// round 7
// speedup vs baseline: 1.1175x; 1.1175x over previous
#include <cuda_runtime.h>
#include <cuda_bf16.h>
#include <cuda_fp8.h>
#include <math.h>
#include <stdint.h>

#define Bsz 8192
#define Gd  1024
#define Ed  256
#define Kd  2048
#define PNULL 0.1f

// ---------------- scratch (device globals; no allocs allowed) ----------------
__device__ __nv_bfloat16  g_pik  [(size_t)Bsz * Kd];    // 32 MB (unnormalized exp)
__device__ __nv_bfloat16  g_w    [(size_t)Bsz * Kd];    // 32 MB: w / u scratch
__device__ __nv_bfloat16  g_z    [(size_t)Bsz * Ed];    // 4 MB
__device__ unsigned char  g_imgs8[(size_t)Bsz * Gd];    // 8 MB fp8 images
__device__ unsigned char  g_xaT8 [(size_t)Kd * Gd];     // 2 MB fp8 (K,G)
__device__ __nv_bfloat16  g_xa   [(size_t)Gd * Kd];     // (G,K) bf16
__device__ __nv_bfloat16  g_xb   [(size_t)Ed * Kd];     // (E,K) bf16
__device__ __nv_bfloat16  g_xbT  [(size_t)Kd * Ed];     // (K,E) bf16
__device__ float g_c2a[Kd], g_c2b[Kd], g_sums[Bsz], g_z2[Bsz];

// ---------------- helpers ----------------
__device__ __forceinline__ uint32_t s2u(const void* p) {
    uint32_t a;
    asm("{ .reg .u64 t; cvta.to.shared.u64 t, %1; cvt.u32.u64 %0, t; }" : "=r"(a) : "l"(p));
    return a;
}
#define SWZ(o) ((o) ^ (((o) >> 3) & 0x70))

__device__ __forceinline__ void cp16(uint32_t dst, const void* src) {
    asm volatile("cp.async.cg.shared.global [%0], [%1], 16;" :: "r"(dst), "l"(src));
}
#define CP_COMMIT()   asm volatile("cp.async.commit_group;" ::: "memory")
#define CP_WAIT(n)    asm volatile("cp.async.wait_group %0;" :: "n"(n) : "memory")

#define LDSM4(r, addr)                                                              \
    asm volatile("ldmatrix.sync.aligned.m8n8.x4.shared.b16 {%0,%1,%2,%3}, [%4];"    \
        : "=r"((r)[0]), "=r"((r)[1]), "=r"((r)[2]), "=r"((r)[3]) : "r"(addr))

#define MMA(d, a, b0, b1)                                                           \
    asm volatile("mma.sync.aligned.m16n8k16.row.col.f32.bf16.bf16.f32 "             \
        "{%0,%1,%2,%3}, {%4,%5,%6,%7}, {%8,%9}, {%0,%1,%2,%3};"                     \
        : "+f"((d)[0]), "+f"((d)[1]), "+f"((d)[2]), "+f"((d)[3])                    \
        : "r"((a)[0]), "r"((a)[1]), "r"((a)[2]), "r"((a)[3]), "r"(b0), "r"(b1))

#define MMA8(d, a, b0, b1)                                                          \
    asm volatile("mma.sync.aligned.m16n8k32.row.col.f32.e4m3.e4m3.f32 "             \
        "{%0,%1,%2,%3}, {%4,%5,%6,%7}, {%8,%9}, {%0,%1,%2,%3};"                     \
        : "+f"((d)[0]), "+f"((d)[1]), "+f"((d)[2]), "+f"((d)[3])                    \
        : "r"((a)[0]), "r"((a)[1]), "r"((a)[2]), "r"((a)[3]), "r"(b0), "r"(b1))

// ---------------- mma.sync GEMM, byte-addressed operands ----------------
// Tile D[(MI*64) x 128]. A: M rows x kbytes (K-major). B: N rows x kbytes (K-major).
// A 128-byte k-chunk = 4 x (k16 bf16 | k32 fp8) steps; fragment byte layout identical.
// MI=1: 64x128 tile, 3 CTA/SM (z-GEMMs).  MI=2: 128x128 tile, 2 CTA/SM.
// EPI 0: e = exp(acc*alpha - c2[n]); out=e (bf16); redout[m] += sum_n e   (pik gen)
//     1: out = acc / rowvec[m]                                            (z)
//     2: w = pik[m,n]*exp(acc*alpha - c2[n]); out=w; redout[m] += sum w   (w)
//     3: u = exp(acc*alpha - c2[n] - rowvec[m]); out=u; redout[m] += sum  (u, rowvec=z2)
//     4: d = acc/(PNULL+rowvec[m]) - images[m,n]; redout[m] += d^2/G      (loss)
//     5: t = acc / rowvec[m]; out=t; redout[m] += t^2/E                   (z + z2)
template <int MI, int FP8, int EPI>
__global__ void __launch_bounds__(256, (MI == 2) ? 2 : 3)
mma_gemm(const void* __restrict__ Av, const void* __restrict__ Bv,
         int kbytes, int lda_b, int ldb_b, int ldc, float alpha,
         __nv_bfloat16* __restrict__ out_bf16,
         const __nv_bfloat16* __restrict__ pik,
         const float* __restrict__ c2vec, const float* __restrict__ rowvec,
         const float* __restrict__ images, float* __restrict__ redout)
{
    extern __shared__ char smem[];
    constexpr int MTILE = MI * 64;
    constexpr uint32_t A_ST = MTILE * 128;          // bytes per A stage
    constexpr uint32_t B_OFF = 3 * A_ST;            // B stages base
    const char* A = (const char*)Av;
    const char* Bm = (const char*)Bv;
    const uint32_t sb = s2u(smem);
    const int tid = threadIdx.x, wid = tid >> 5, lane = tid & 31;
    const int m0 = blockIdx.y * MTILE, n0 = blockIdx.x * 128;
    const int wm = (wid & 3) * (MI * 16), wn = (wid >> 2) * 64;

    float acc[MI][8][4];
#pragma unroll
    for (int i = 0; i < MI; i++)
#pragma unroll
        for (int j = 0; j < 8; j++)
#pragma unroll
            for (int q = 0; q < 4; q++) acc[i][j][q] = 0.f;

    auto loadA = [&](int c, int st) {
        // stage = MTILE rows x 128 B = MTILE*8 units of 16B; 256 thr -> MI*2 per thread
#pragma unroll
        for (int u = 0; u < MI * 2; u++) {
            int unit = tid + u * 256;
            int row = unit >> 3, seg = unit & 7;
            cp16(sb + st * A_ST + SWZ((uint32_t)(row * 128 + seg * 16)),
                 A + (size_t)(m0 + row) * lda_b + c * 128 + seg * 16);
        }
    };
    auto loadB = [&](int c, int st) {
#pragma unroll
        for (int u = 0; u < 4; u++) {
            int unit = tid + u * 256;                      // 128 rows x 8 segs
            int row = unit >> 3, seg = unit & 7;
            cp16(sb + B_OFF + st * 16384 + SWZ((uint32_t)(row * 128 + seg * 16)),
                 Bm + (size_t)(n0 + row) * ldb_b + c * 128 + seg * 16);
        }
    };

    const int nch = kbytes >> 7;
    loadA(0, 0); loadB(0, 0); CP_COMMIT();
    if (nch > 1) { loadA(1, 1); loadB(1, 1); CP_COMMIT(); }

    const int lr = lane & 15, lc = (lane >> 4) * 16;

    for (int c = 0; c < nch; c++) {
        if (c == nch - 1) { CP_WAIT(0); } else { CP_WAIT(1); }
        __syncthreads();                       // stage c visible; stage (c+2)%3 compute done
        if (c + 2 < nch) {
            loadA(c + 2, (c + 2) % 3); loadB(c + 2, (c + 2) % 3); CP_COMMIT();
        }
        const int st = c % 3;
        const uint32_t sA = sb + st * A_ST;
        const uint32_t sB = sb + B_OFF + st * 16384;
#pragma unroll
        for (int kk = 0; kk < 4; kk++) {
            const int kb = kk * 32 + lc;
            uint32_t a[MI][4], b[4][4];
#pragma unroll
            for (int mi = 0; mi < MI; mi++)
                LDSM4(a[mi], sA + SWZ((uint32_t)((wm + mi * 16 + lr) * 128 + kb)));
#pragma unroll
            for (int pi = 0; pi < 4; pi++)
                LDSM4(b[pi], sB + SWZ((uint32_t)((wn + pi * 16 + lr) * 128 + kb)));
#pragma unroll
            for (int mi = 0; mi < MI; mi++)
#pragma unroll
                for (int ni = 0; ni < 8; ni++) {
                    const int pi = ni >> 1, sel = ni & 1;
                    if (FP8) MMA8(acc[mi][ni], a[mi], b[pi][sel], b[pi][sel + 2]);
                    else     MMA(acc[mi][ni], a[mi], b[pi][sel], b[pi][sel + 2]);
                }
        }
    }

    // ---- epilogue ----
    const int g = lane >> 2, cq = lane & 3;
    constexpr float rscale = (EPI == 4) ? 1.0f / Gd : (EPI == 5) ? 1.0f / Ed : 1.0f;
#pragma unroll
    for (int mi = 0; mi < MI; mi++) {
        const int r0 = m0 + wm + mi * 16 + g;
        const int r1 = r0 + 8;
        float rv0 = 1.f, rv1 = 1.f;
        if (EPI == 1 || EPI == 5) { rv0 = 1.0f / rowvec[r0]; rv1 = 1.0f / rowvec[r1]; }
        if (EPI == 3) { rv0 = rowvec[r0]; rv1 = rowvec[r1]; }
        if (EPI == 4) { rv0 = 1.0f / (PNULL + rowvec[r0]); rv1 = 1.0f / (PNULL + rowvec[r1]); }
        float ls0 = 0.f, ls1 = 0.f;
#pragma unroll
        for (int ni = 0; ni < 8; ni++) {
            const int col = n0 + wn + ni * 8 + cq * 2;
            float v00 = acc[mi][ni][0], v01 = acc[mi][ni][1];
            float v10 = acc[mi][ni][2], v11 = acc[mi][ni][3];
            size_t i0 = (size_t)r0 * ldc + col, i1 = (size_t)r1 * ldc + col;
            if (EPI == 0) {
                float c0 = c2vec[col], c1 = c2vec[col + 1];
                float e00 = expf(v00 * alpha - c0), e01 = expf(v01 * alpha - c1);
                float e10 = expf(v10 * alpha - c0), e11 = expf(v11 * alpha - c1);
                *(__nv_bfloat162*)(out_bf16 + i0) = __floats2bfloat162_rn(e00, e01);
                *(__nv_bfloat162*)(out_bf16 + i1) = __floats2bfloat162_rn(e10, e11);
                ls0 += e00 + e01; ls1 += e10 + e11;
            } else if (EPI == 1) {
                *(__nv_bfloat162*)(out_bf16 + i0) = __floats2bfloat162_rn(v00 * rv0, v01 * rv0);
                *(__nv_bfloat162*)(out_bf16 + i1) = __floats2bfloat162_rn(v10 * rv1, v11 * rv1);
            } else if (EPI == 5) {
                float t00 = v00 * rv0, t01 = v01 * rv0;
                float t10 = v10 * rv1, t11 = v11 * rv1;
                *(__nv_bfloat162*)(out_bf16 + i0) = __floats2bfloat162_rn(t00, t01);
                *(__nv_bfloat162*)(out_bf16 + i1) = __floats2bfloat162_rn(t10, t11);
                ls0 += t00 * t00 + t01 * t01; ls1 += t10 * t10 + t11 * t11;
            } else if (EPI == 2) {
                float c0 = c2vec[col], c1 = c2vec[col + 1];
                __nv_bfloat162 p0 = *(const __nv_bfloat162*)(pik + i0);
                __nv_bfloat162 p1 = *(const __nv_bfloat162*)(pik + i1);
                float w00 = __bfloat162float(p0.x) * expf(v00 * alpha - c0);
                float w01 = __bfloat162float(p0.y) * expf(v01 * alpha - c1);
                float w10 = __bfloat162float(p1.x) * expf(v10 * alpha - c0);
                float w11 = __bfloat162float(p1.y) * expf(v11 * alpha - c1);
                *(__nv_bfloat162*)(out_bf16 + i0) = __floats2bfloat162_rn(w00, w01);
                *(__nv_bfloat162*)(out_bf16 + i1) = __floats2bfloat162_rn(w10, w11);
                ls0 += w00 + w01; ls1 += w10 + w11;
            } else if (EPI == 3) {
                float c0 = c2vec[col], c1 = c2vec[col + 1];
                float u00 = expf(v00 * alpha - c0 - rv0), u01 = expf(v01 * alpha - c1 - rv0);
                float u10 = expf(v10 * alpha - c0 - rv1), u11 = expf(v11 * alpha - c1 - rv1);
                *(__nv_bfloat162*)(out_bf16 + i0) = __floats2bfloat162_rn(u00, u01);
                *(__nv_bfloat162*)(out_bf16 + i1) = __floats2bfloat162_rn(u10, u11);
                ls0 += u00 + u01; ls1 += u10 + u11;
            } else {  // EPI 4
                float d;
                d = v00 * rv0 - images[i0];     ls0 += d * d;
                d = v01 * rv0 - images[i0 + 1]; ls0 += d * d;
                d = v10 * rv1 - images[i1];     ls1 += d * d;
                d = v11 * rv1 - images[i1 + 1]; ls1 += d * d;
            }
        }
        if (EPI != 1) {
            ls0 += __shfl_xor_sync(0xffffffffu, ls0, 1);
            ls0 += __shfl_xor_sync(0xffffffffu, ls0, 2);
            ls1 += __shfl_xor_sync(0xffffffffu, ls1, 1);
            ls1 += __shfl_xor_sync(0xffffffffu, ls1, 2);
            if (cq == 0) {
                atomicAdd(&redout[r0], ls0 * rscale);
                atomicAdd(&redout[r1], ls1 * rscale);
            }
        }
    }
}

// ---------------- small kernels ----------------
__global__ void k_cvt4(const float4* __restrict__ s, __nv_bfloat162* __restrict__ d, int n4) {
    int i = blockIdx.x * blockDim.x + threadIdx.x;
    if (i < n4) {
        float4 v = s[i];
        d[2 * i]     = __floats2bfloat162_rn(v.x, v.y);
        d[2 * i + 1] = __floats2bfloat162_rn(v.z, v.w);
    }
}
__global__ void k_cvt8(const float4* __restrict__ s, uint32_t* __restrict__ d, int n4) {
    int i = blockIdx.x * blockDim.x + threadIdx.x;
    if (i < n4) {
        float4 v = s[i];
        uint32_t lo = __nv_cvt_float2_to_fp8x2(make_float2(v.x, v.y), __NV_SATFINITE, __NV_E4M3);
        uint32_t hi = __nv_cvt_float2_to_fp8x2(make_float2(v.z, v.w), __NV_SATFINITE, __NV_E4M3);
        d[i] = (hi << 16) | (lo & 0xFFFFu);
    }
}
// tiled transpose+convert: dst (C,R) bf16 = src (R,C)^T fp32
__global__ void k_tcvtT(const float* __restrict__ s, __nv_bfloat16* __restrict__ d, int R, int C) {
    __shared__ float t[32][33];
    int c0 = blockIdx.x * 32, r0 = blockIdx.y * 32;
    int tx = threadIdx.x, ty = threadIdx.y;       // block (32,8)
#pragma unroll
    for (int j = 0; j < 32; j += 8) t[ty + j][tx] = s[(size_t)(r0 + ty + j) * C + c0 + tx];
    __syncthreads();
#pragma unroll
    for (int j = 0; j < 32; j += 8)
        d[(size_t)(c0 + ty + j) * R + r0 + tx] = __float2bfloat16(t[tx][ty + j]);
}
// tiled transpose+convert to fp8
__global__ void k_tcvtT8(const float* __restrict__ s, unsigned char* __restrict__ d, int R, int C) {
    __shared__ float t[32][33];
    int c0 = blockIdx.x * 32, r0 = blockIdx.y * 32;
    int tx = threadIdx.x, ty = threadIdx.y;
#pragma unroll
    for (int j = 0; j < 32; j += 8) t[ty + j][tx] = s[(size_t)(r0 + ty + j) * C + c0 + tx];
    __syncthreads();
#pragma unroll
    for (int j = 0; j < 32; j += 8)
        d[(size_t)(c0 + ty + j) * R + r0 + tx] =
            (unsigned char)__nv_cvt_float_to_fp8(t[tx][ty + j], __NV_SATFINITE, __NV_E4M3);
}
// c2 column squared-means, 2D-parallel with atomics (requires pre-zeroed output)
__global__ void k_c2p(const float* __restrict__ x, float* __restrict__ out,
                      int rows, int rows_per_blk, float inv) {
    int k = blockIdx.x * blockDim.x + threadIdx.x;
    int r0 = blockIdx.y * rows_per_blk;
    float s = 0.f;
    for (int r = r0; r < r0 + rows_per_blk; r++) {
        float v = x[(size_t)r * Kd + k];
        s += v * v;
    }
    atomicAdd(&out[k], s * inv);
}

// ---------------- host ----------------
extern "C" void kernel_launch(void* const* d_in, const int* in_sizes, int n_in,
                              void* d_out, int out_size) {
    (void)in_sizes; (void)n_in; (void)out_size;
    const float* images = (const float*)d_in[0];
    const float* xa     = (const float*)d_in[1];
    const float* xb     = (const float*)d_in[2];
    float* loss = (float*)d_out;

    float *c2a, *c2b, *sums, *z2;
    __nv_bfloat16 *pik, *wb, *zb, *xab, *xbb, *xbT;
    unsigned char *imgs8, *xaT8;
    cudaGetSymbolAddress((void**)&pik,   g_pik);
    cudaGetSymbolAddress((void**)&wb,    g_w);
    cudaGetSymbolAddress((void**)&zb,    g_z);
    cudaGetSymbolAddress((void**)&imgs8, g_imgs8);
    cudaGetSymbolAddress((void**)&xaT8,  g_xaT8);
    cudaGetSymbolAddress((void**)&xab,   g_xa);
    cudaGetSymbolAddress((void**)&xbb,   g_xb);
    cudaGetSymbolAddress((void**)&xbT,   g_xbT);
    cudaGetSymbolAddress((void**)&c2a,   g_c2a);
    cudaGetSymbolAddress((void**)&c2b,   g_c2b);
    cudaGetSymbolAddress((void**)&sums,  g_sums);
    cudaGetSymbolAddress((void**)&z2,    g_z2);

    const int SMEM1 = 3 * (64 * 128) + 3 * 16384;    // 72 KB (MI=1)
    const int SMEM2 = 3 * (128 * 128) + 3 * 16384;   // 96 KB (MI=2)
    cudaFuncSetAttribute(mma_gemm<2, 1, 0>, cudaFuncAttributeMaxDynamicSharedMemorySize, SMEM2);
    cudaFuncSetAttribute(mma_gemm<1, 0, 1>, cudaFuncAttributeMaxDynamicSharedMemorySize, SMEM1);
    cudaFuncSetAttribute(mma_gemm<2, 0, 2>, cudaFuncAttributeMaxDynamicSharedMemorySize, SMEM2);
    cudaFuncSetAttribute(mma_gemm<2, 0, 3>, cudaFuncAttributeMaxDynamicSharedMemorySize, SMEM2);
    cudaFuncSetAttribute(mma_gemm<2, 0, 4>, cudaFuncAttributeMaxDynamicSharedMemorySize, SMEM2);
    cudaFuncSetAttribute(mma_gemm<1, 0, 5>, cudaFuncAttributeMaxDynamicSharedMemorySize, SMEM1);

    // one-time conversions
    k_cvt8<<<(Bsz * Gd / 4 + 255) / 256, 256>>>((const float4*)images, (uint32_t*)imgs8, Bsz * Gd / 4);
    k_tcvtT8<<<dim3(Kd / 32, Gd / 32), dim3(32, 8)>>>(xa, xaT8, Gd, Kd);          // (K,G) fp8
    k_cvt4<<<(Gd * Kd / 4 + 255) / 256, 256>>>((const float4*)xa, (__nv_bfloat162*)xab, Gd * Kd / 4);
    k_cvt4<<<(Ed * Kd / 4 + 255) / 256, 256>>>((const float4*)xb, (__nv_bfloat162*)xbb, Ed * Kd / 4);
    k_tcvtT<<<dim3(Kd / 32, Ed / 32), dim3(32, 8)>>>(xb, xbT, Ed, Kd);            // (K,E) bf16
    cudaMemsetAsync(c2a, 0, Kd * sizeof(float));
    cudaMemsetAsync(c2b, 0, Kd * sizeof(float));
    k_c2p<<<dim3(Kd / 256, 8), 256>>>(xa, c2a, Gd, Gd / 8, 1.0f / Gd);
    k_c2p<<<dim3(Kd / 256, 2), 256>>>(xb, c2b, Ed, Ed / 2, 1.0f / Ed);

    dim3 gK(Kd / 128, Bsz / 128);   // (16,64) MI=2
    dim3 gE(Ed / 128, Bsz / 64);    // (2,128) MI=1
    dim3 gG(Gd / 128, Bsz / 128);   // (8,64)  MI=2

    // pik_unnorm = exp(images@xa*2/G - c2a) [fp8 GEMM], sums = softmax denominators
    cudaMemsetAsync(sums, 0, Bsz * sizeof(float));
    mma_gemm<2, 1, 0><<<gK, 256, SMEM2>>>(imgs8, xaT8, Gd, Gd, Gd, Kd, 2.0f / Gd,
                                          pik, nullptr, c2a, nullptr, nullptr, sums);
    // z = (pik_unnorm @ xb^T) / sums
    mma_gemm<1, 0, 1><<<gE, 256, SMEM1>>>(pik, xbb, Kd * 2, Kd * 2, Kd * 2, Ed, 1.0f,
                                          zb, nullptr, nullptr, sums, nullptr, nullptr);
    // 4 EM steps; P_NULL and exp(-z2) row constants cancel in xp = w/sum(w)
    for (int s = 0; s < 4; s++) {
        cudaMemsetAsync(sums, 0, Bsz * sizeof(float));
        // w = pik * exp((z@xb)*2/E - c2b); sums = row sums(w)
        mma_gemm<2, 0, 2><<<gK, 256, SMEM2>>>(zb, xbT, Ed * 2, Ed * 2, Ed * 2, Kd, 2.0f / Ed,
                                              wb, pik, c2b, nullptr, nullptr, sums);
        if (s < 3) {
            mma_gemm<1, 0, 1><<<gE, 256, SMEM1>>>(wb, xbb, Kd * 2, Kd * 2, Kd * 2, Ed, 1.0f,
                                                  zb, nullptr, nullptr, sums, nullptr, nullptr);
        } else {
            cudaMemsetAsync(z2, 0, Bsz * sizeof(float));
            mma_gemm<1, 0, 5><<<gE, 256, SMEM1>>>(wb, xbb, Kd * 2, Kd * 2, Kd * 2, Ed, 1.0f,
                                                  zb, nullptr, nullptr, sums, nullptr, z2);
        }
    }
    // decode: u = exp((z@xb)*2/E - c2b - z2); sums = row sums(u)
    cudaMemsetAsync(sums, 0, Bsz * sizeof(float));
    mma_gemm<2, 0, 3><<<gK, 256, SMEM2>>>(zb, xbT, Ed * 2, Ed * 2, Ed * 2, Kd, 2.0f / Ed,
                                          wb, nullptr, c2b, z2, nullptr, sums);
    // loss[b] = mean_g ((u/(0.1+sums)) @ xa^T - images)^2
    cudaMemsetAsync(loss, 0, Bsz * sizeof(float));
    mma_gemm<2, 0, 4><<<gG, 256, SMEM2>>>(wb, xab, Kd * 2, Kd * 2, Kd * 2, Gd, 1.0f,
                                          nullptr, nullptr, nullptr, sums, images, loss);
}